// round 1
// baseline (speedup 1.0000x reference)
#include <cuda_runtime.h>
#include <math.h>

// Problem constants
// B=4, N=4096, DIM=1024, HEADS=16, HEAD_DIM=64, FEAT=256
// qkv: (16384 x 3072), per-(b,h) matrices over 64 bh pairs.

// ---------------- scratch (device globals; no allocations allowed) ---------
__device__ float g_qkv  [(size_t)16384 * 3072];   // 192 MB
__device__ float g_qproj[(size_t)64 * 4096 * 256]; // 256 MB
__device__ float g_kproj[(size_t)64 * 4096 * 256]; // 256 MB
__device__ float g_kv   [64 * 256 * 64];           // 4 MB
__device__ float g_ksum [64 * 256];
__device__ float g_z    [64 * 4096];
__device__ float g_attn [(size_t)16384 * 1024];    // 64 MB

// ---------------- zero kv/ksum (must be re-zeroed every call) --------------
__global__ void k_zero_kv() {
    int i = blockIdx.x * 256 + threadIdx.x;
    if (i < 64 * 256 * 64) g_kv[i] = 0.f;
    if (i < 64 * 256)      g_ksum[i] = 0.f;
}

// ---------------- GEMM 1: qkv = x @ w_qkv   (16384x1024)@(1024x3072) -------
__global__ void k_gemm_qkv(const float* __restrict__ X, const float* __restrict__ W) {
    const int K = 1024, Nc = 3072;
    __shared__ float As[16][68];
    __shared__ float Bs[16][64];
    int bm = blockIdx.y * 64, bn = blockIdx.x * 64;
    int tid = threadIdx.x;
    int tx = tid & 15, ty = tid >> 4;
    float acc[4][4] = {};
    for (int k0 = 0; k0 < K; k0 += 16) {
#pragma unroll
        for (int i = 0; i < 4; i++) {
            int idx = tid + i * 256; int r = idx >> 4, c = idx & 15;
            As[c][r] = X[(size_t)(bm + r) * K + k0 + c];
        }
#pragma unroll
        for (int i = 0; i < 4; i++) {
            int idx = tid + i * 256; int r = idx >> 6, c = idx & 63;
            Bs[r][c] = W[(size_t)(k0 + r) * Nc + bn + c];
        }
        __syncthreads();
#pragma unroll
        for (int kk = 0; kk < 16; kk++) {
            float a[4], b[4];
#pragma unroll
            for (int i = 0; i < 4; i++) a[i] = As[kk][ty * 4 + i];
#pragma unroll
            for (int j = 0; j < 4; j++) b[j] = Bs[kk][tx * 4 + j];
#pragma unroll
            for (int i = 0; i < 4; i++)
#pragma unroll
                for (int j = 0; j < 4; j++) acc[i][j] = fmaf(a[i], b[j], acc[i][j]);
        }
        __syncthreads();
    }
#pragma unroll
    for (int i = 0; i < 4; i++)
#pragma unroll
        for (int j = 0; j < 4; j++)
            g_qkv[(size_t)(bm + ty * 4 + i) * Nc + bn + tx * 4 + j] = acc[i][j];
}

// ---------------- proj + elu1: per (b,h): (4096x64)@(64x256) ---------------
// qk_off: 0 for Q, 1024 for K.  which: 0 -> g_qproj, 1 -> g_kproj
__global__ void k_proj(const float* __restrict__ P, int qk_off, int which) {
    int bh = blockIdx.z; int b = bh >> 4, h = bh & 15;
    int bm = blockIdx.y * 64, bn = blockIdx.x * 64;
    const float* A  = g_qkv + (size_t)b * 4096 * 3072 + qk_off + h * 64; // row stride 3072
    const float* Bp = P + (size_t)h * 64 * 256;                          // row stride 256
    float* C = (which ? g_kproj : g_qproj) + (size_t)bh * 4096 * 256;
    __shared__ float As[16][68];
    __shared__ float Bs[16][64];
    int tid = threadIdx.x, tx = tid & 15, ty = tid >> 4;
    float acc[4][4] = {};
    for (int k0 = 0; k0 < 64; k0 += 16) {
#pragma unroll
        for (int i = 0; i < 4; i++) {
            int idx = tid + i * 256; int r = idx >> 4, c = idx & 15;
            As[c][r] = A[(size_t)(bm + r) * 3072 + k0 + c];
        }
#pragma unroll
        for (int i = 0; i < 4; i++) {
            int idx = tid + i * 256; int r = idx >> 6, c = idx & 63;
            Bs[r][c] = Bp[(k0 + r) * 256 + bn + c];
        }
        __syncthreads();
#pragma unroll
        for (int kk = 0; kk < 16; kk++) {
            float a[4], b[4];
#pragma unroll
            for (int i = 0; i < 4; i++) a[i] = As[kk][ty * 4 + i];
#pragma unroll
            for (int j = 0; j < 4; j++) b[j] = Bs[kk][tx * 4 + j];
#pragma unroll
            for (int i = 0; i < 4; i++)
#pragma unroll
                for (int j = 0; j < 4; j++) acc[i][j] = fmaf(a[i], b[j], acc[i][j]);
        }
        __syncthreads();
    }
#pragma unroll
    for (int i = 0; i < 4; i++)
#pragma unroll
        for (int j = 0; j < 4; j++) {
            float v = acc[i][j];
            v = (v > 0.f) ? (v + 1.f) : expf(v);   // elu(x)+1
            C[(size_t)(bm + ty * 4 + i) * 256 + bn + tx * 4 + j] = v;
        }
}

// ---------------- kv state: kv[f,d] += sum_n kproj[n,f]*v[n,d] (split-K) ---
__global__ void k_kvacc() {
    int bh = blockIdx.z; int b = bh >> 4, h = bh & 15;
    int f0 = blockIdx.x * 64;
    int n0 = blockIdx.y * 512;
    const float* A = g_kproj + (size_t)bh * 4096 * 256;                 // [n, f]
    const float* V = g_qkv + (size_t)b * 4096 * 3072 + 2048 + h * 64;   // [n, d] stride 3072
    float* C = g_kv + bh * 256 * 64;
    __shared__ float As[16][64];  // [kk][f] (already naturally transposed)
    __shared__ float Bs[16][64];  // [kk][d]
    int tid = threadIdx.x, tx = tid & 15, ty = tid >> 4;
    float acc[4][4] = {};
    for (int k0 = 0; k0 < 512; k0 += 16) {
        int n = n0 + k0;
#pragma unroll
        for (int i = 0; i < 4; i++) {
            int idx = tid + i * 256; int r = idx >> 6, c = idx & 63;
            As[r][c] = A[(size_t)(n + r) * 256 + f0 + c];
        }
#pragma unroll
        for (int i = 0; i < 4; i++) {
            int idx = tid + i * 256; int r = idx >> 6, c = idx & 63;
            Bs[r][c] = V[(size_t)(n + r) * 3072 + c];
        }
        __syncthreads();
#pragma unroll
        for (int kk = 0; kk < 16; kk++) {
            float a[4], b[4];
#pragma unroll
            for (int i = 0; i < 4; i++) a[i] = As[kk][ty * 4 + i];
#pragma unroll
            for (int j = 0; j < 4; j++) b[j] = Bs[kk][tx * 4 + j];
#pragma unroll
            for (int i = 0; i < 4; i++)
#pragma unroll
                for (int j = 0; j < 4; j++) acc[i][j] = fmaf(a[i], b[j], acc[i][j]);
        }
        __syncthreads();
    }
#pragma unroll
    for (int i = 0; i < 4; i++)
#pragma unroll
        for (int j = 0; j < 4; j++)
            atomicAdd(&C[(f0 + ty * 4 + i) * 64 + tx * 4 + j], acc[i][j]);
}

// ---------------- k_sum[b,h,f] = sum_n kproj[n,f] (split over n) -----------
__global__ void k_ksum() {
    int bh = blockIdx.x, chunk = blockIdx.y;
    int f = threadIdx.x;
    const float* A = g_kproj + (size_t)bh * 4096 * 256;
    float s = 0.f;
    for (int n = chunk * 256; n < chunk * 256 + 256; n++)
        s += A[(size_t)n * 256 + f];
    atomicAdd(&g_ksum[bh * 256 + f], s);
}

// ---------------- z[b,h,n] = 1/(dot(qproj[n,:], ksum) + 1e-8) --------------
__global__ void k_zcalc() {
    int bh = blockIdx.y;
    int warp = threadIdx.x >> 5, lane = threadIdx.x & 31;
    int n = blockIdx.x * 8 + warp;
    const float* q  = g_qproj + ((size_t)bh * 4096 + n) * 256;
    const float* ks = g_ksum + bh * 256;
    float s = 0.f;
    for (int f = lane; f < 256; f += 32) s = fmaf(q[f], ks[f], s);
#pragma unroll
    for (int o = 16; o; o >>= 1) s += __shfl_xor_sync(0xFFFFFFFFu, s, o);
    if (lane == 0) g_z[bh * 4096 + n] = 1.f / (s + 1e-8f);
}

// ---------------- attn: per (b,h): (4096x256)@(256x64), scale by z ---------
__global__ void k_attn() {
    int bh = blockIdx.z; int b = bh >> 4, h = bh & 15;
    int bm = blockIdx.y * 64;
    const float* A  = g_qproj + (size_t)bh * 4096 * 256;
    const float* Bm = g_kv + bh * 256 * 64;
    float* C = g_attn + (size_t)b * 4096 * 1024 + h * 64;
    __shared__ float As[16][68];
    __shared__ float Bs[16][64];
    int tid = threadIdx.x, tx = tid & 15, ty = tid >> 4;
    float acc[4][4] = {};
    for (int k0 = 0; k0 < 256; k0 += 16) {
#pragma unroll
        for (int i = 0; i < 4; i++) {
            int idx = tid + i * 256; int r = idx >> 4, c = idx & 15;
            As[c][r] = A[(size_t)(bm + r) * 256 + k0 + c];
        }
#pragma unroll
        for (int i = 0; i < 4; i++) {
            int idx = tid + i * 256; int r = idx >> 6, c = idx & 63;
            Bs[r][c] = Bm[(k0 + r) * 64 + c];
        }
        __syncthreads();
#pragma unroll
        for (int kk = 0; kk < 16; kk++) {
            float a[4], b[4];
#pragma unroll
            for (int i = 0; i < 4; i++) a[i] = As[kk][ty * 4 + i];
#pragma unroll
            for (int j = 0; j < 4; j++) b[j] = Bs[kk][tx * 4 + j];
#pragma unroll
            for (int i = 0; i < 4; i++)
#pragma unroll
                for (int j = 0; j < 4; j++) acc[i][j] = fmaf(a[i], b[j], acc[i][j]);
        }
        __syncthreads();
    }
#pragma unroll
    for (int i = 0; i < 4; i++) {
        int row = bm + ty * 4 + i;
        float z = g_z[bh * 4096 + row];
#pragma unroll
        for (int j = 0; j < 4; j++)
            C[(size_t)row * 1024 + tx * 4 + j] = acc[i][j] * z;
    }
}

// ---------------- GEMM 2: out = attn @ w_out + b_out  (16384x1024)@(1024x1024)
__global__ void k_gemm_out(const float* __restrict__ W, const float* __restrict__ bias,
                           float* __restrict__ OUT) {
    const int K = 1024, Nc = 1024;
    __shared__ float As[16][68];
    __shared__ float Bs[16][64];
    int bm = blockIdx.y * 64, bn = blockIdx.x * 64;
    int tid = threadIdx.x;
    int tx = tid & 15, ty = tid >> 4;
    float acc[4][4] = {};
    for (int k0 = 0; k0 < K; k0 += 16) {
#pragma unroll
        for (int i = 0; i < 4; i++) {
            int idx = tid + i * 256; int r = idx >> 4, c = idx & 15;
            As[c][r] = g_attn[(size_t)(bm + r) * K + k0 + c];
        }
#pragma unroll
        for (int i = 0; i < 4; i++) {
            int idx = tid + i * 256; int r = idx >> 6, c = idx & 63;
            Bs[r][c] = W[(size_t)(k0 + r) * Nc + bn + c];
        }
        __syncthreads();
#pragma unroll
        for (int kk = 0; kk < 16; kk++) {
            float a[4], b[4];
#pragma unroll
            for (int i = 0; i < 4; i++) a[i] = As[kk][ty * 4 + i];
#pragma unroll
            for (int j = 0; j < 4; j++) b[j] = Bs[kk][tx * 4 + j];
#pragma unroll
            for (int i = 0; i < 4; i++)
#pragma unroll
                for (int j = 0; j < 4; j++) acc[i][j] = fmaf(a[i], b[j], acc[i][j]);
        }
        __syncthreads();
    }
#pragma unroll
    for (int i = 0; i < 4; i++)
#pragma unroll
        for (int j = 0; j < 4; j++)
            OUT[(size_t)(bm + ty * 4 + i) * Nc + bn + tx * 4 + j] =
                acc[i][j] + bias[bn + tx * 4 + j];
}

// ---------------- launch ---------------------------------------------------
extern "C" void kernel_launch(void* const* d_in, const int* in_sizes, int n_in,
                              void* d_out, int out_size) {
    const float* x      = (const float*)d_in[0];   // (4,4096,1024)
    const float* w_qkv  = (const float*)d_in[1];   // (1024,3072)
    const float* proj   = (const float*)d_in[2];   // (16,64,256)
    const float* w_out  = (const float*)d_in[3];   // (1024,1024)
    const float* b_out  = (const float*)d_in[4];   // (1024,)
    float* out = (float*)d_out;

    // 1. zero kv/ksum scratch
    k_zero_kv<<<4096, 256>>>();
    // 2. qkv = x @ w_qkv
    k_gemm_qkv<<<dim3(48, 256), 256>>>(x, w_qkv);
    // 3. q_proj / k_proj (+elu1)
    k_proj<<<dim3(4, 64, 64), 256>>>(proj, 0,    0);  // Q
    k_proj<<<dim3(4, 64, 64), 256>>>(proj, 1024, 1);  // K
    // 4. kv state (split-K atomics)
    k_kvacc<<<dim3(4, 8, 64), 256>>>();
    // 5. k_sum
    k_ksum<<<dim3(64, 16), 256>>>();
    // 6. z normalizer
    k_zcalc<<<dim3(512, 64), 256>>>();
    // 7. attn = qproj @ kv, scaled by z -> g_attn (b,n,dim layout)
    k_attn<<<dim3(1, 64, 64), 256>>>();
    // 8. out = attn @ w_out + b_out
    k_gemm_out<<<dim3(16, 256), 256>>>(w_out, b_out, out);
}

// round 15
// speedup vs baseline: 1.4990x; 1.4990x over previous
#include <cuda_runtime.h>
#include <mma.h>
#include <cstdint>
#include <math.h>

using namespace nvcuda;

// B=4, N=4096, DIM=1024, HEADS=16, HEAD_DIM=64, FEAT=256
// Round 15 (resubmit of R11-R14; infra timeouts): wmma tf32 for the two K=1024
// GEMMs; round-1 verbatim FFMA for proj / kv / ksum / z / attn.

// ---------------- scratch (device globals) ---------------------------------
__device__ float g_qkv   [(size_t)16384 * 3072];
__device__ float g_qproj [(size_t)64 * 4096 * 256];    // [bh][n][f]
__device__ float g_kproj [(size_t)64 * 4096 * 256];    // [bh][n][f]
__device__ float g_kv    [64 * 256 * 64];              // [bh][f][d]
__device__ float g_ksum  [64 * 256];
__device__ float g_z     [64 * 4096];
__device__ float g_attn  [(size_t)16384 * 1024];

#define DEVINL __device__ __forceinline__

// ---------------- wmma tf32 GEMM: C(128x128) = A(128xK) @ W(KxNc) ----------
// A row-major (lda), W row-major (ldw). 8 warps: 2 (M) x 4 (N); warp tile 64x32.
DEVINL void wmma_gemm(const float* __restrict__ A, int lda,
                      const float* __restrict__ W, int ldw, int K,
                      float* __restrict__ C, int ldc) {
    __shared__ float As[128 * 20];   // [m][k], padded ld 20
    __shared__ float Bs[16 * 132];   // [k][n], padded ld 132
    const int tid = threadIdx.x;
    const int warp = tid >> 5;
    const int wm = warp & 1, wn = warp >> 1;   // 2 x 4 warp grid

    wmma::fragment<wmma::accumulator, 16, 16, 8, float> cf[4][2];
#pragma unroll
    for (int mt = 0; mt < 4; mt++)
#pragma unroll
        for (int nt = 0; nt < 2; nt++) wmma::fill_fragment(cf[mt][nt], 0.0f);

    for (int k0 = 0; k0 < K; k0 += 16) {
        // A tile: 128 rows x 16 floats = 512 float4 over 256 threads
#pragma unroll
        for (int i = 0; i < 2; i++) {
            int idx = tid + i * 256; int r = idx >> 2, c = idx & 3;
            *(float4*)&As[r * 20 + c * 4] = *(const float4*)(A + (size_t)r * lda + k0 + c * 4);
        }
        // B tile: 16 rows x 128 floats = 512 float4
#pragma unroll
        for (int i = 0; i < 2; i++) {
            int idx = tid + i * 256; int r = idx >> 5, c = idx & 31;
            *(float4*)&Bs[r * 132 + c * 4] = *(const float4*)(W + (size_t)(k0 + r) * ldw + c * 4);
        }
        __syncthreads();
#pragma unroll
        for (int ks = 0; ks < 16; ks += 8) {
            wmma::fragment<wmma::matrix_a, 16, 16, 8, wmma::precision::tf32, wmma::row_major> af[4];
            wmma::fragment<wmma::matrix_b, 16, 16, 8, wmma::precision::tf32, wmma::row_major> bf[2];
#pragma unroll
            for (int mt = 0; mt < 4; mt++) {
                wmma::load_matrix_sync(af[mt], &As[(wm * 64 + mt * 16) * 20 + ks], 20);
#pragma unroll
                for (int t = 0; t < af[mt].num_elements; t++)
                    af[mt].x[t] = wmma::__float_to_tf32(af[mt].x[t]);
            }
#pragma unroll
            for (int nt = 0; nt < 2; nt++) {
                wmma::load_matrix_sync(bf[nt], &Bs[ks * 132 + wn * 32 + nt * 16], 132);
#pragma unroll
                for (int t = 0; t < bf[nt].num_elements; t++)
                    bf[nt].x[t] = wmma::__float_to_tf32(bf[nt].x[t]);
            }
#pragma unroll
            for (int mt = 0; mt < 4; mt++)
#pragma unroll
                for (int nt = 0; nt < 2; nt++)
                    wmma::mma_sync(cf[mt][nt], af[mt], bf[nt], cf[mt][nt]);
        }
        __syncthreads();
    }
#pragma unroll
    for (int mt = 0; mt < 4; mt++)
#pragma unroll
        for (int nt = 0; nt < 2; nt++)
            wmma::store_matrix_sync(C + (size_t)(wm * 64 + mt * 16) * ldc + wn * 32 + nt * 16,
                                    cf[mt][nt], ldc, wmma::mem_row_major);
}

// qkv = x @ w_qkv : (16384x1024)@(1024x3072)
__global__ __launch_bounds__(256, 2) void k_gemm_qkv_w(const float* __restrict__ X,
                                                       const float* __restrict__ W) {
    int bm = blockIdx.y * 128, bn = blockIdx.x * 128;
    wmma_gemm(X + (size_t)bm * 1024, 1024, W + bn, 3072, 1024,
              g_qkv + (size_t)bm * 3072 + bn, 3072);
}

// out = attn @ w_out : (16384x1024)@(1024x1024)   (bias added separately)
__global__ __launch_bounds__(256, 2) void k_gemm_out_w(const float* __restrict__ W,
                                                       float* __restrict__ OUT) {
    int bm = blockIdx.y * 128, bn = blockIdx.x * 128;
    wmma_gemm(g_attn + (size_t)bm * 1024, 1024, W + bn, 1024, 1024,
              OUT + (size_t)bm * 1024 + bn, 1024);
}

__global__ void k_bias(const float* __restrict__ bias, float* __restrict__ OUT) {
    size_t i = (size_t)blockIdx.x * 256 + threadIdx.x;   // 16384*1024 elements
    OUT[i] += bias[i & 1023];
}

// ================= round-1 verbatim FFMA middle + back half ================
__global__ void k_proj(const float* __restrict__ P, int qk_off, int which) {
    int bh = blockIdx.z; int b = bh >> 4, h = bh & 15;
    int bm = blockIdx.y * 64, bn = blockIdx.x * 64;
    const float* A  = g_qkv + (size_t)b * 4096 * 3072 + qk_off + h * 64; // row stride 3072
    const float* Bp = P + (size_t)h * 64 * 256;                          // row stride 256
    float* C = (which ? g_kproj : g_qproj) + (size_t)bh * 4096 * 256;
    __shared__ float As[16][68];
    __shared__ float Bs[16][64];
    int tid = threadIdx.x, tx = tid & 15, ty = tid >> 4;
    float acc[4][4] = {};
    for (int k0 = 0; k0 < 64; k0 += 16) {
#pragma unroll
        for (int i = 0; i < 4; i++) {
            int idx = tid + i * 256; int r = idx >> 4, c = idx & 15;
            As[c][r] = A[(size_t)(bm + r) * 3072 + k0 + c];
        }
#pragma unroll
        for (int i = 0; i < 4; i++) {
            int idx = tid + i * 256; int r = idx >> 6, c = idx & 63;
            Bs[r][c] = Bp[(k0 + r) * 256 + bn + c];
        }
        __syncthreads();
#pragma unroll
        for (int kk = 0; kk < 16; kk++) {
            float a[4], b[4];
#pragma unroll
            for (int i = 0; i < 4; i++) a[i] = As[kk][ty * 4 + i];
#pragma unroll
            for (int j = 0; j < 4; j++) b[j] = Bs[kk][tx * 4 + j];
#pragma unroll
            for (int i = 0; i < 4; i++)
#pragma unroll
                for (int j = 0; j < 4; j++) acc[i][j] = fmaf(a[i], b[j], acc[i][j]);
        }
        __syncthreads();
    }
#pragma unroll
    for (int i = 0; i < 4; i++)
#pragma unroll
        for (int j = 0; j < 4; j++) {
            float v = acc[i][j];
            v = (v > 0.f) ? (v + 1.f) : expf(v);   // elu(x)+1
            C[(size_t)(bm + ty * 4 + i) * 256 + bn + tx * 4 + j] = v;
        }
}

__global__ void k_zero_kv() {
    int i = blockIdx.x * 256 + threadIdx.x;
    if (i < 64 * 256 * 64) g_kv[i] = 0.f;
    if (i < 64 * 256)      g_ksum[i] = 0.f;
}

__global__ void k_kvacc() {
    int bh = blockIdx.z; int b = bh >> 4, h = bh & 15;
    int f0 = blockIdx.x * 64;
    int n0 = blockIdx.y * 512;
    const float* A = g_kproj + (size_t)bh * 4096 * 256;                 // [n, f]
    const float* V = g_qkv + (size_t)b * 4096 * 3072 + 2048 + h * 64;   // [n, d] stride 3072
    float* C = g_kv + bh * 256 * 64;
    __shared__ float As[16][64];
    __shared__ float Bs[16][64];
    int tid = threadIdx.x, tx = tid & 15, ty = tid >> 4;
    float acc[4][4] = {};
    for (int k0 = 0; k0 < 512; k0 += 16) {
        int n = n0 + k0;
#pragma unroll
        for (int i = 0; i < 4; i++) {
            int idx = tid + i * 256; int r = idx >> 6, c = idx & 63;
            As[r][c] = A[(size_t)(n + r) * 256 + f0 + c];
        }
#pragma unroll
        for (int i = 0; i < 4; i++) {
            int idx = tid + i * 256; int r = idx >> 6, c = idx & 63;
            Bs[r][c] = V[(size_t)(n + r) * 3072 + c];
        }
        __syncthreads();
#pragma unroll
        for (int kk = 0; kk < 16; kk++) {
            float a[4], b[4];
#pragma unroll
            for (int i = 0; i < 4; i++) a[i] = As[kk][ty * 4 + i];
#pragma unroll
            for (int j = 0; j < 4; j++) b[j] = Bs[kk][tx * 4 + j];
#pragma unroll
            for (int i = 0; i < 4; i++)
#pragma unroll
                for (int j = 0; j < 4; j++) acc[i][j] = fmaf(a[i], b[j], acc[i][j]);
        }
        __syncthreads();
    }
#pragma unroll
    for (int i = 0; i < 4; i++)
#pragma unroll
        for (int j = 0; j < 4; j++)
            atomicAdd(&C[(f0 + ty * 4 + i) * 64 + tx * 4 + j], acc[i][j]);
}

__global__ void k_ksum() {
    int bh = blockIdx.x, chunk = blockIdx.y;
    int f = threadIdx.x;
    const float* A = g_kproj + (size_t)bh * 4096 * 256;
    float s = 0.f;
    for (int n = chunk * 256; n < chunk * 256 + 256; n++)
        s += A[(size_t)n * 256 + f];
    atomicAdd(&g_ksum[bh * 256 + f], s);
}

__global__ void k_zcalc() {
    int bh = blockIdx.y;
    int warp = threadIdx.x >> 5, lane = threadIdx.x & 31;
    int n = blockIdx.x * 8 + warp;
    const float* q  = g_qproj + ((size_t)bh * 4096 + n) * 256;
    const float* ks = g_ksum + bh * 256;
    float s = 0.f;
    for (int f = lane; f < 256; f += 32) s = fmaf(q[f], ks[f], s);
#pragma unroll
    for (int o = 16; o; o >>= 1) s += __shfl_xor_sync(0xFFFFFFFFu, s, o);
    if (lane == 0) g_z[bh * 4096 + n] = 1.f / (s + 1e-8f);
}

__global__ void k_attn() {
    int bh = blockIdx.z; int b = bh >> 4, h = bh & 15;
    int bm = blockIdx.y * 64;
    const float* A  = g_qproj + (size_t)bh * 4096 * 256;
    const float* Bm = g_kv + bh * 256 * 64;
    float* C = g_attn + (size_t)b * 4096 * 1024 + h * 64;
    __shared__ float As[16][68];
    __shared__ float Bs[16][64];
    int tid = threadIdx.x, tx = tid & 15, ty = tid >> 4;
    float acc[4][4] = {};
    for (int k0 = 0; k0 < 256; k0 += 16) {
#pragma unroll
        for (int i = 0; i < 4; i++) {
            int idx = tid + i * 256; int r = idx >> 4, c = idx & 15;
            As[c][r] = A[(size_t)(bm + r) * 256 + k0 + c];
        }
#pragma unroll
        for (int i = 0; i < 4; i++) {
            int idx = tid + i * 256; int r = idx >> 6, c = idx & 63;
            Bs[r][c] = Bm[(k0 + r) * 64 + c];
        }
        __syncthreads();
#pragma unroll
        for (int kk = 0; kk < 16; kk++) {
            float a[4], b[4];
#pragma unroll
            for (int i = 0; i < 4; i++) a[i] = As[kk][ty * 4 + i];
#pragma unroll
            for (int j = 0; j < 4; j++) b[j] = Bs[kk][tx * 4 + j];
#pragma unroll
            for (int i = 0; i < 4; i++)
#pragma unroll
                for (int j = 0; j < 4; j++) acc[i][j] = fmaf(a[i], b[j], acc[i][j]);
        }
        __syncthreads();
    }
#pragma unroll
    for (int i = 0; i < 4; i++) {
        int row = bm + ty * 4 + i;
        float z = g_z[bh * 4096 + row];
#pragma unroll
        for (int j = 0; j < 4; j++)
            C[(size_t)row * 1024 + tx * 4 + j] = acc[i][j] * z;
    }
}

// ---------------- launch ----------------------------------------------------
extern "C" void kernel_launch(void* const* d_in, const int* in_sizes, int n_in,
                              void* d_out, int out_size) {
    const float* x     = (const float*)d_in[0];   // (4,4096,1024)
    const float* w_qkv = (const float*)d_in[1];   // (1024,3072)
    const float* proj  = (const float*)d_in[2];   // (16,64,256)
    const float* w_out = (const float*)d_in[3];   // (1024,1024)
    const float* b_out = (const float*)d_in[4];   // (1024,)
    float* out = (float*)d_out;

    k_gemm_qkv_w<<<dim3(24, 128), 256>>>(x, w_qkv);   // wmma tf32

    k_proj<<<dim3(4, 64, 64), 256>>>(proj, 0,    0);  // round-1 FFMA, Q
    k_proj<<<dim3(4, 64, 64), 256>>>(proj, 1024, 1);  // round-1 FFMA, K

    k_zero_kv<<<4096, 256>>>();
    k_kvacc<<<dim3(4, 8, 64), 256>>>();
    k_ksum<<<dim3(64, 16), 256>>>();
    k_zcalc<<<dim3(512, 64), 256>>>();
    k_attn<<<dim3(1, 64, 64), 256>>>();

    k_gemm_out_w<<<dim3(8, 128), 256>>>(w_out, out);  // wmma tf32
    k_bias<<<65536, 256>>>(b_out, out);
}